// round 3
// baseline (speedup 1.0000x reference)
#include <cuda_runtime.h>
#include <cstdint>

#define TT    140
#define HH    128
#define G4    512
#define BT    32          // batches per CTA
#define NCTA  128
#define NTHR  256
#define KC    32          // k per streamed W chunk
#define CHUNK_FLOATS (KC*G4)                 // 16384 floats (64KB)
#define OFF_H2  (2*CHUNK_FLOATS)             // h2[b][k] duplicated pairs: 32*128*2
#define OFF_X   (OFF_H2 + BT*HH*2)           // x_sh[t*32+b]: 140*32
#define OFF_WB  (OFF_X + TT*BT)              // wb_sh[u][8]
#define SMEM_FLOATS (OFF_WB + HH*8)
#define SMEM_BYTES  (SMEM_FLOATS*4)

// ---- persistent device scratch (no runtime alloc) ----
__device__ float g_Wg[HH*G4];    // [k][u][4 gates i,f,g,o]
__device__ float g_wb[HH*8];     // [u][wi,wf,wg,wo, bi,bf,bg,bo]
__device__ float g_W1t[HH*HH];   // W1 transposed: [k][n]

// ---- helpers ----
__device__ __forceinline__ unsigned long long packdup(float v){
    unsigned long long r;
    asm("mov.b64 %0,{%1,%1};" : "=l"(r) : "f"(v));
    return r;
}
__device__ __forceinline__ void unpack2(unsigned long long v, float& lo, float& hi){
    asm("mov.b64 {%0,%1},%2;" : "=f"(lo), "=f"(hi) : "l"(v));
}
__device__ __forceinline__ unsigned long long ffma2(unsigned long long a,
                                                    unsigned long long b,
                                                    unsigned long long c){
    unsigned long long d;
    asm("fma.rn.f32x2 %0,%1,%2,%3;" : "=l"(d) : "l"(a), "l"(b), "l"(c));
    return d;
}
__device__ __forceinline__ float fast_sigmoid(float x){
    float e, r;
    asm("ex2.approx.f32 %0,%1;" : "=f"(e) : "f"(-1.4426950408889634f * x));
    asm("rcp.approx.f32 %0,%1;" : "=f"(r) : "f"(1.0f + e));
    return r;
}
__device__ __forceinline__ float fast_tanh(float x){
    float e, r;
    asm("ex2.approx.f32 %0,%1;" : "=f"(e) : "f"(2.8853900817779268f * x));
    asm("rcp.approx.f32 %0,%1;" : "=f"(r) : "f"(1.0f + e));
    return 1.0f - 2.0f * r;
}
__device__ __forceinline__ void cp_async16(void* smem_ptr, const void* gmem_ptr){
    unsigned s = (unsigned)__cvta_generic_to_shared(smem_ptr);
    asm volatile("cp.async.cg.shared.global [%0],[%1],16;" :: "r"(s), "l"(gmem_ptr));
}
__device__ __forceinline__ void cp_commit(){
    asm volatile("cp.async.commit_group;" ::: "memory");
}
template<int N>
__device__ __forceinline__ void cp_wait(){
    asm volatile("cp.async.wait_group %0;" :: "n"(N) : "memory");
}
__device__ __forceinline__ void copy_chunk(float* wbuf, int chunk, int buf, int tid){
    const float* src = g_Wg + chunk * CHUNK_FLOATS;
    float* dst = wbuf + buf * CHUNK_FLOATS;
    #pragma unroll
    for (int i = 0; i < CHUNK_FLOATS/(4*NTHR); i++){
        int idx = (tid + i*NTHR) * 4;
        cp_async16(dst + idx, src + idx);
    }
}

// ---- prep: re-layout weights ----
__global__ void prep_kernel(const float* __restrict__ Whh,
                            const float* __restrict__ Wih,
                            const float* __restrict__ bih,
                            const float* __restrict__ bhh,
                            const float* __restrict__ W1){
    int i = blockIdx.x * blockDim.x + threadIdx.x;
    int stride = gridDim.x * blockDim.x;
    for (int idx = i; idx < HH*G4; idx += stride){
        int k = idx >> 9;            // /512
        int r = idx & 511;
        int u = r >> 2, g = r & 3;
        g_Wg[idx] = Whh[(g*HH + u)*HH + k];
    }
    for (int idx = i; idx < HH*8; idx += stride){
        int u = idx >> 3, s = idx & 7;
        int g = s & 3;
        int j = g*HH + u;
        g_wb[idx] = (s < 4) ? Wih[j] : (bih[j] + bhh[j]);
    }
    for (int idx = i; idx < HH*HH; idx += stride){
        int k = idx >> 7, n = idx & 127;
        g_W1t[idx] = W1[n*HH + k];
    }
}

// ---- main persistent LSTM kernel ----
__global__ __launch_bounds__(NTHR, 1)
void lstm_kernel(const float* __restrict__ x,
                 const float* __restrict__ b1,
                 const float* __restrict__ W2,
                 const float* __restrict__ b2,
                 float* __restrict__ out){
    extern __shared__ float sm[];
    float* wbuf  = sm;               // [2][KC*512]
    float* h2    = sm + OFF_H2;      // [b][k] dup pairs
    float* x_sh  = sm + OFF_X;       // [t][b]
    float* wb_sh = sm + OFF_WB;      // [u][8]

    const int tid  = threadIdx.x;
    const int lane = tid & 31;
    const int warp = tid >> 5;       // 0..7
    const int ug   = warp & 3;       // 0..3
    const int bg   = warp >> 2;      // 0..1
    const int u    = ug*32 + lane;   // 0..127
    const int bb   = bg * 16;        // first of 16 batches
    const int b0   = blockIdx.x * BT;

    // stage x: x_sh[t*32+b]
    for (int idx = tid; idx < BT*TT; idx += NTHR){
        int t = idx >> 5, b = idx & 31;
        x_sh[t*32 + b] = x[(size_t)(b0 + b)*TT + t];
    }
    for (int idx = tid; idx < BT*HH*2; idx += NTHR) h2[idx] = 0.0f;
    for (int idx = tid; idx < HH*8;    idx += NTHR) wb_sh[idx] = g_wb[idx];
    __syncthreads();

    const ulonglong2 wv = *(const ulonglong2*)&wb_sh[u*8];     // (w_if, w_go)
    const ulonglong2 bv = *(const ulonglong2*)&wb_sh[u*8 + 4]; // (b_if, b_go)

    copy_chunk(wbuf, 0, 0, tid); cp_commit();
    copy_chunk(wbuf, 1, 1, tid); cp_commit();

    float c_reg[16];
    #pragma unroll
    for (int b = 0; b < 16; b++) c_reg[b] = 0.0f;

    int next = 2;
    for (int t = 0; t < TT; t++){
        unsigned long long aif[16], ago[16];
        {
            float4 xq[4];
            #pragma unroll
            for (int i = 0; i < 4; i++)
                xq[i] = *(const float4*)&x_sh[t*32 + bb + 4*i];
            const float xv[16] = {xq[0].x,xq[0].y,xq[0].z,xq[0].w,
                                  xq[1].x,xq[1].y,xq[1].z,xq[1].w,
                                  xq[2].x,xq[2].y,xq[2].z,xq[2].w,
                                  xq[3].x,xq[3].y,xq[3].z,xq[3].w};
            #pragma unroll
            for (int b = 0; b < 16; b++){
                unsigned long long x2 = packdup(xv[b]);
                aif[b] = ffma2(x2, wv.x, bv.x);
                ago[b] = ffma2(x2, wv.y, bv.y);
            }
        }

        #pragma unroll 1
        for (int c = 0; c < 4; c++){
            cp_wait<1>();
            __syncthreads();
            const float* wb = wbuf + (c & 1)*CHUNK_FLOATS;
            const float* hb = h2 + bb*HH*2 + c*KC*2;
            #pragma unroll 4
            for (int kq = 0; kq < KC/2; kq++){
                ulonglong2 wA = *(const ulonglong2*)&wb[(2*kq  )*G4 + u*4];
                ulonglong2 wB = *(const ulonglong2*)&wb[(2*kq+1)*G4 + u*4];
                #pragma unroll
                for (int b = 0; b < 16; b++){
                    // {h[k]dup, h[k+1]dup} for batch bb+b
                    ulonglong2 hh = *(const ulonglong2*)&hb[b*HH*2 + kq*4];
                    aif[b] = ffma2(hh.x, wA.x, aif[b]);
                    ago[b] = ffma2(hh.x, wA.y, ago[b]);
                    aif[b] = ffma2(hh.y, wB.x, aif[b]);
                    ago[b] = ffma2(hh.y, wB.y, ago[b]);
                }
            }
            __syncthreads();
            copy_chunk(wbuf, next & 3, c & 1, tid);
            cp_commit();
            next++;
        }

        // elementwise LSTM update; write dup h pairs (conflict-light STS.64)
        #pragma unroll
        for (int b = 0; b < 16; b++){
            float gi, gf, gg, go;
            unpack2(aif[b], gi, gf);
            unpack2(ago[b], gg, go);
            float iv = fast_sigmoid(gi);
            float fv = fast_sigmoid(gf);
            float gv = fast_tanh(gg);
            float ov = fast_sigmoid(go);
            float cv = fv * c_reg[b] + iv * gv;
            c_reg[b] = cv;
            float hval = ov * fast_tanh(cv);
            *(float2*)&h2[(bb + b)*HH*2 + u*2] = make_float2(hval, hval);
        }
        // ordering vs next step's reads: the cp_wait+__syncthreads at chunk 0
    }

    cp_wait<0>();
    __syncthreads();

    // ---- tail: r1 = relu(h@W1^T + b1) ----
    // stage W1t (64KB) into wbuf buf0
    #pragma unroll
    for (int i = 0; i < CHUNK_FLOATS/(4*NTHR); i++){
        int idx = (tid + i*NTHR)*4;
        cp_async16(wbuf + idx, g_W1t + idx);
    }
    cp_commit();
    cp_wait<0>();
    __syncthreads();

    float r1[16];
    {
        float bn = b1[u];
        #pragma unroll
        for (int b = 0; b < 16; b++) r1[b] = bn;
    }
    #pragma unroll 4
    for (int k = 0; k < HH; k++){
        float w = wbuf[k*HH + u];
        #pragma unroll
        for (int b = 0; b < 16; b++){
            float hv = h2[(bb + b)*HH*2 + k*2];
            r1[b] = fmaf(hv, w, r1[b]);
        }
    }
    __syncthreads();
    // write relu(r1) into x_sh region reused as r1_sh[b][n] (32*128 <= 140*32)
    float* r1_sh = x_sh;
    #pragma unroll
    for (int b = 0; b < 16; b++)
        r1_sh[(bb + b)*HH + u] = fmaxf(r1[b], 0.0f);
    // stage W2 (5x128) into wb_sh region (1024 floats >= 640)
    for (int idx = tid; idx < 5*HH; idx += NTHR) wb_sh[idx] = W2[idx];
    __syncthreads();

    // ---- r2 = r1@W2^T + b2; log_softmax ----
    if (tid < BT){
        const int b = tid;
        float r2[5];
        #pragma unroll
        for (int o = 0; o < 5; o++) r2[o] = b2[o];
        for (int kk = 0; kk < HH; kk++){
            int k = (kk + b*4) & (HH - 1);   // stagger: avoid 32-way conflicts
            float v = r1_sh[b*HH + k];
            #pragma unroll
            for (int o = 0; o < 5; o++) r2[o] = fmaf(v, wb_sh[o*HH + k], r2[o]);
        }
        float m = r2[0];
        #pragma unroll
        for (int o = 1; o < 5; o++) m = fmaxf(m, r2[o]);
        float s = 0.f;
        #pragma unroll
        for (int o = 0; o < 5; o++) s += __expf(r2[o] - m);
        float l = m + __logf(s);
        #pragma unroll
        for (int o = 0; o < 5; o++)
            out[(size_t)(b0 + b)*5 + o] = r2[o] - l;
    }
}

extern "C" void kernel_launch(void* const* d_in, const int* in_sizes, int n_in,
                              void* d_out, int out_size){
    const float* x   = (const float*)d_in[0];
    const float* Wih = (const float*)d_in[1];
    const float* Whh = (const float*)d_in[2];
    const float* bih = (const float*)d_in[3];
    const float* bhh = (const float*)d_in[4];
    const float* W1  = (const float*)d_in[5];
    const float* b1  = (const float*)d_in[6];
    const float* W2  = (const float*)d_in[7];
    const float* b2  = (const float*)d_in[8];
    float* out = (float*)d_out;

    prep_kernel<<<64, 256>>>(Whh, Wih, bih, bhh, W1);

    cudaFuncSetAttribute(lstm_kernel,
                         cudaFuncAttributeMaxDynamicSharedMemorySize, SMEM_BYTES);
    lstm_kernel<<<NCTA, NTHR, SMEM_BYTES>>>(x, b1, W2, b2, out);
}

// round 5
// speedup vs baseline: 5.8711x; 5.8711x over previous
#include <cuda_runtime.h>
#include <cuda_fp16.h>
#include <cstdint>

#define TT 140
#define HH 128
#define BT 32
#define NCTA 128
#define NTHR 256

#define WSTRIDE 136                    // halfs per weight row (272 B, conflict-free LDSM)
#define WROWS   640                    // 512 gate rows + 128 W1 rows
#define WBYTES  (WROWS*WSTRIDE*2)      // 174080
#define HSTRIDE 40                     // halfs per h row (80 B, conflict-free)
#define HBYTES  (HH*HSTRIDE*2)         // 10240
#define OFF_W   0
#define OFF_H   WBYTES                 // two h buffers
#define OFF_X   (OFF_H + 2*HBYTES)     // x_sh [t][b] f32 (17920 B); reused as r1_sh in tail
#define SMEM_BYTES (OFF_X + TT*BT*4)   // 212480

// f16 weights, padded layout: rows 0..511 = W_hh (gate-major), rows 512..639 = W1
__device__ __align__(16) unsigned short g_W16[WROWS*WSTRIDE];

// ---------------- helpers ----------------
__device__ __forceinline__ uint32_t smem_u32(const void* p){
    uint32_t a;
    asm("{ .reg .u64 t; cvta.to.shared.u64 t, %1; cvt.u32.u64 %0, t; }"
        : "=r"(a) : "l"(p));
    return a;
}
__device__ __forceinline__ void cp_async16(void* s, const void* g){
    unsigned a = smem_u32(s);
    asm volatile("cp.async.cg.shared.global [%0],[%1],16;" :: "r"(a), "l"(g));
}
__device__ __forceinline__ void ldsm4(uint32_t* r, uint32_t addr){
    asm volatile("ldmatrix.sync.aligned.m8n8.x4.shared.b16 {%0,%1,%2,%3},[%4];"
        : "=r"(r[0]),"=r"(r[1]),"=r"(r[2]),"=r"(r[3]) : "r"(addr));
}
__device__ __forceinline__ void ldsm4t(uint32_t* r, uint32_t addr){
    asm volatile("ldmatrix.sync.aligned.m8n8.x4.trans.shared.b16 {%0,%1,%2,%3},[%4];"
        : "=r"(r[0]),"=r"(r[1]),"=r"(r[2]),"=r"(r[3]) : "r"(addr));
}
__device__ __forceinline__ void mma16816(float* d, const uint32_t* a,
                                         uint32_t b0, uint32_t b1){
    asm volatile("mma.sync.aligned.m16n8k16.row.col.f32.f16.f16.f32 "
        "{%0,%1,%2,%3},{%4,%5,%6,%7},{%8,%9},{%0,%1,%2,%3};"
        : "+f"(d[0]),"+f"(d[1]),"+f"(d[2]),"+f"(d[3])
        : "r"(a[0]),"r"(a[1]),"r"(a[2]),"r"(a[3]),"r"(b0),"r"(b1));
}
__device__ __forceinline__ float fast_sigmoid(float x){
    float e, r;
    asm("ex2.approx.f32 %0,%1;" : "=f"(e) : "f"(-1.4426950408889634f * x));
    asm("rcp.approx.f32 %0,%1;" : "=f"(r) : "f"(1.0f + e));
    return r;
}
__device__ __forceinline__ float fast_tanh(float x){
    float e, r;
    asm("ex2.approx.f32 %0,%1;" : "=f"(e) : "f"(2.8853900817779268f * x));
    asm("rcp.approx.f32 %0,%1;" : "=f"(r) : "f"(1.0f + e));
    return 1.0f - 2.0f * r;
}

// ---------------- prep: convert weights to f16 padded layout ----------------
__global__ void prep_kernel(const float* __restrict__ Whh,
                            const float* __restrict__ W1){
    int i = blockIdx.x * blockDim.x + threadIdx.x;
    int stride = gridDim.x * blockDim.x;
    for (int idx = i; idx < WROWS*HH; idx += stride){
        int row = idx >> 7, k = idx & 127;
        float v = (row < 512) ? Whh[row*HH + k] : W1[(row - 512)*HH + k];
        __half hv = __float2half_rn(v);
        g_W16[row*WSTRIDE + k] = *(unsigned short*)&hv;
    }
}

// ---------------- main persistent LSTM kernel ----------------
__global__ __launch_bounds__(NTHR, 1)
void lstm_kernel(const float* __restrict__ x,
                 const float* __restrict__ Wih,
                 const float* __restrict__ bih,
                 const float* __restrict__ bhh,
                 const float* __restrict__ b1,
                 const float* __restrict__ W2,
                 const float* __restrict__ b2,
                 float* __restrict__ out){
    extern __shared__ char sm[];
    const uint32_t smb = smem_u32(sm);
    const int tid  = threadIdx.x;
    const int lane = tid & 31;
    const int w    = tid >> 5;          // warp 0..7, owns units 16w..16w+15
    const int b0   = blockIdx.x * BT;
    float* x_sh = (float*)(sm + OFF_X);

    // ---- stage W (f16, 174080 B) via cp.async; x; zero h buffer 0 ----
    for (int i = tid*16; i < WBYTES; i += NTHR*16)
        cp_async16(sm + OFF_W + i, (const char*)g_W16 + i);
    asm volatile("cp.async.commit_group;" ::: "memory");
    for (int idx = tid; idx < TT*BT; idx += NTHR){
        int t = idx >> 5, b = idx & 31;
        x_sh[t*32 + b] = x[(size_t)(b0 + b)*TT + t];
    }
    for (int i = tid; i < HBYTES/4; i += NTHR)
        ((float*)(sm + OFF_H))[i] = 0.0f;
    asm volatile("cp.async.wait_group 0;" ::: "memory");
    __syncthreads();

    // ---- per-thread constants ----
    const int u0 = 16*w + (lane >> 2);
    const int u1 = u0 + 8;
    float wi[4][2], bs[4][2];
    #pragma unroll
    for (int g = 0; g < 4; g++){
        wi[g][0] = Wih[g*HH + u0];
        wi[g][1] = Wih[g*HH + u1];
        bs[g][0] = bih[g*HH + u0] + bhh[g*HH + u0];
        bs[g][1] = bih[g*HH + u1] + bhh[g*HH + u1];
    }
    float c0[8], c1[8];
    #pragma unroll
    for (int i = 0; i < 8; i++){ c0[i] = 0.0f; c1[i] = 0.0f; }

    // ldmatrix address bases
    uint32_t Abase[4];
    #pragma unroll
    for (int mt = 0; mt < 4; mt++)
        Abase[mt] = smb + OFF_W +
            (uint32_t)(((mt*128 + 16*w + (lane & 15))*WSTRIDE + (lane >> 4)*8) * 2);
    const uint32_t AbaseT = smb + OFF_W +
            (uint32_t)(((512 + 16*w + (lane & 15))*WSTRIDE + (lane >> 4)*8) * 2);
    const uint32_t Brow = (uint32_t)((lane & 7) + ((lane >> 3) & 1)*8);
    const uint32_t Bb0  = smb + OFF_H + Brow*(HSTRIDE*2) + (uint32_t)((lane >> 4)*8)*2;
    const uint32_t Bb1  = Bb0 + 32;     // n0 = 16
    const int bq = 2*(lane & 3);        // batch base within n8 tile

    uint32_t bsel = 0;                  // byte offset of current read h buffer
    for (int t = 0; t < TT; t++){
        // init accumulators with bias + x_t * w_in
        float acc[4][4][4];
        float xv[4][2];
        #pragma unroll
        for (int nt = 0; nt < 4; nt++){
            xv[nt][0] = x_sh[t*32 + 8*nt + bq];
            xv[nt][1] = x_sh[t*32 + 8*nt + bq + 1];
        }
        #pragma unroll
        for (int mt = 0; mt < 4; mt++)
            #pragma unroll
            for (int nt = 0; nt < 4; nt++){
                acc[mt][nt][0] = fmaf(xv[nt][0], wi[mt][0], bs[mt][0]);
                acc[mt][nt][1] = fmaf(xv[nt][1], wi[mt][0], bs[mt][0]);
                acc[mt][nt][2] = fmaf(xv[nt][0], wi[mt][1], bs[mt][1]);
                acc[mt][nt][3] = fmaf(xv[nt][1], wi[mt][1], bs[mt][1]);
            }

        // gates += W @ h   (K = 128, 8 k-chunks)
        const uint32_t Bc0 = Bb0 + bsel, Bc1 = Bb1 + bsel;
        #pragma unroll
        for (int kc = 0; kc < 8; kc++){
            uint32_t bfr0[4], bfr1[4];
            ldsm4t(bfr0, Bc0 + kc*(16*HSTRIDE*2));
            ldsm4t(bfr1, Bc1 + kc*(16*HSTRIDE*2));
            #pragma unroll
            for (int mt = 0; mt < 4; mt++){
                uint32_t a[4];
                ldsm4(a, Abase[mt] + kc*32);
                mma16816(acc[mt][0], a, bfr0[0], bfr0[1]);
                mma16816(acc[mt][1], a, bfr0[2], bfr0[3]);
                mma16816(acc[mt][2], a, bfr1[0], bfr1[1]);
                mma16816(acc[mt][3], a, bfr1[2], bfr1[3]);
            }
        }

        // elementwise LSTM update (all 4 gates thread-local), write h to other buffer
        const uint32_t wsel = bsel ^ HBYTES;
        #pragma unroll
        for (int nt = 0; nt < 4; nt++){
            float hv0[2], hv1[2];
            #pragma unroll
            for (int j = 0; j < 2; j++){
                int ci = nt*2 + j;
                {   // unit u0
                    float iv = fast_sigmoid(acc[0][nt][j]);
                    float fv = fast_sigmoid(acc[1][nt][j]);
                    float gv = fast_tanh   (acc[2][nt][j]);
                    float ov = fast_sigmoid(acc[3][nt][j]);
                    float cv = fv * c0[ci] + iv * gv;
                    c0[ci] = cv;
                    hv0[j] = ov * fast_tanh(cv);
                }
                {   // unit u1
                    float iv = fast_sigmoid(acc[0][nt][2+j]);
                    float fv = fast_sigmoid(acc[1][nt][2+j]);
                    float gv = fast_tanh   (acc[2][nt][2+j]);
                    float ov = fast_sigmoid(acc[3][nt][2+j]);
                    float cv = fv * c1[ci] + iv * gv;
                    c1[ci] = cv;
                    hv1[j] = ov * fast_tanh(cv);
                }
            }
            int boff = (8*nt + bq)*2;
            *(half2*)(sm + OFF_H + wsel + u0*(HSTRIDE*2) + boff) =
                __floats2half2_rn(hv0[0], hv0[1]);
            *(half2*)(sm + OFF_H + wsel + u1*(HSTRIDE*2) + boff) =
                __floats2half2_rn(hv1[0], hv1[1]);
        }
        __syncthreads();
        bsel = wsel;
    }
    // final h is in buffer with byte-offset bsel (= 0 for TT even)

    // ---- MLP head: r1 = relu(W1 @ h + b1) via the same MMA path ----
    float racc[4][4];
    {
        float bv0 = b1[u0], bv1 = b1[u1];
        #pragma unroll
        for (int nt = 0; nt < 4; nt++){
            racc[nt][0] = bv0; racc[nt][1] = bv0;
            racc[nt][2] = bv1; racc[nt][3] = bv1;
        }
    }
    {
        const uint32_t Bc0 = Bb0 + bsel, Bc1 = Bb1 + bsel;
        #pragma unroll
        for (int kc = 0; kc < 8; kc++){
            uint32_t bfr0[4], bfr1[4];
            ldsm4t(bfr0, Bc0 + kc*(16*HSTRIDE*2));
            ldsm4t(bfr1, Bc1 + kc*(16*HSTRIDE*2));
            uint32_t a[4];
            ldsm4(a, AbaseT + kc*32);
            mma16816(racc[0], a, bfr0[0], bfr0[1]);
            mma16816(racc[1], a, bfr0[2], bfr0[3]);
            mma16816(racc[2], a, bfr1[0], bfr1[1]);
            mma16816(racc[3], a, bfr1[2], bfr1[3]);
        }
    }
    __syncthreads();            // x_sh reads done; reuse as r1_sh
    float* r1_sh = (float*)(sm + OFF_X);   // [b][n] f32
    #pragma unroll
    for (int nt = 0; nt < 4; nt++)
        #pragma unroll
        for (int j = 0; j < 2; j++){
            int b = 8*nt + bq + j;
            r1_sh[b*HH + u0] = fmaxf(racc[nt][j],     0.0f);
            r1_sh[b*HH + u1] = fmaxf(racc[nt][2 + j], 0.0f);
        }
    __syncthreads();
    // stage W2 (5x128 f32) into h region (done with h)
    float* w2sh = (float*)(sm + OFF_H);
    for (int idx = tid; idx < 5*HH; idx += NTHR) w2sh[idx] = W2[idx];
    __syncthreads();

    // ---- r2 = r1 @ W2^T + b2; log_softmax (one thread per batch) ----
    if (tid < BT){
        const int b = tid;
        float r2[5];
        #pragma unroll
        for (int o = 0; o < 5; o++) r2[o] = b2[o];
        for (int kk = 0; kk < HH; kk++){
            int k = (kk + b*4) & (HH - 1);
            float v = r1_sh[b*HH + k];
            #pragma unroll
            for (int o = 0; o < 5; o++) r2[o] = fmaf(v, w2sh[o*HH + k], r2[o]);
        }
        float m = r2[0];
        #pragma unroll
        for (int o = 1; o < 5; o++) m = fmaxf(m, r2[o]);
        float s = 0.0f;
        #pragma unroll
        for (int o = 0; o < 5; o++) s += __expf(r2[o] - m);
        float l = m + __logf(s);
        #pragma unroll
        for (int o = 0; o < 5; o++)
            out[(size_t)(b0 + b)*5 + o] = r2[o] - l;
    }
}

extern "C" void kernel_launch(void* const* d_in, const int* in_sizes, int n_in,
                              void* d_out, int out_size){
    const float* x   = (const float*)d_in[0];
    const float* Wih = (const float*)d_in[1];
    const float* Whh = (const float*)d_in[2];
    const float* bih = (const float*)d_in[3];
    const float* bhh = (const float*)d_in[4];
    const float* W1  = (const float*)d_in[5];
    const float* b1  = (const float*)d_in[6];
    const float* W2  = (const float*)d_in[7];
    const float* b2  = (const float*)d_in[8];
    float* out = (float*)d_out;

    prep_kernel<<<128, 256>>>(Whh, W1);

    cudaFuncSetAttribute(lstm_kernel,
                         cudaFuncAttributeMaxDynamicSharedMemorySize, SMEM_BYTES);
    lstm_kernel<<<NCTA, NTHR, SMEM_BYTES>>>(x, Wih, bih, bhh, b1, W2, b2, out);
}

// round 6
// speedup vs baseline: 7.8899x; 1.3439x over previous
#include <cuda_runtime.h>
#include <cuda_fp16.h>
#include <cstdint>

#define TT 140
#define HH 128
#define BT 32
#define NCTA 128
#define NTHR 256

#define WSTRIDE 136                    // halfs per weight row (272 B, conflict-free LDSM)
#define WROWS   640                    // 512 gate rows + 128 W1 rows
#define WBYTES  (WROWS*WSTRIDE*2)      // 174080
#define HSTRIDE 40                     // halfs per h row (80 B, conflict-free)
#define HBYTES  (HH*HSTRIDE*2)         // 10240
#define OFF_W   0
#define OFF_H   WBYTES                 // two h buffers
#define OFF_X   (OFF_H + 2*HBYTES)     // x_sh [t][b] f32 (17920 B); reused as r1_sh in tail
#define SMEM_BYTES (OFF_X + TT*BT*4)   // 212480

// f16 weights, padded layout: rows 0..511 = W_hh (gate-major), rows 512..639 = W1
__device__ __align__(16) unsigned short g_W16[WROWS*WSTRIDE];

// ---------------- helpers ----------------
__device__ __forceinline__ uint32_t smem_u32(const void* p){
    uint32_t a;
    asm("{ .reg .u64 t; cvta.to.shared.u64 t, %1; cvt.u32.u64 %0, t; }"
        : "=r"(a) : "l"(p));
    return a;
}
__device__ __forceinline__ void cp_async16(void* s, const void* g){
    unsigned a = smem_u32(s);
    asm volatile("cp.async.cg.shared.global [%0],[%1],16;" :: "r"(a), "l"(g));
}
__device__ __forceinline__ void ldsm4(uint32_t* r, uint32_t addr){
    asm volatile("ldmatrix.sync.aligned.m8n8.x4.shared.b16 {%0,%1,%2,%3},[%4];"
        : "=r"(r[0]),"=r"(r[1]),"=r"(r[2]),"=r"(r[3]) : "r"(addr));
}
__device__ __forceinline__ void ldsm4t(uint32_t* r, uint32_t addr){
    asm volatile("ldmatrix.sync.aligned.m8n8.x4.trans.shared.b16 {%0,%1,%2,%3},[%4];"
        : "=r"(r[0]),"=r"(r[1]),"=r"(r[2]),"=r"(r[3]) : "r"(addr));
}
__device__ __forceinline__ void mma16816(float* d, const uint32_t* a,
                                         uint32_t b0, uint32_t b1){
    asm volatile("mma.sync.aligned.m16n8k16.row.col.f32.f16.f16.f32 "
        "{%0,%1,%2,%3},{%4,%5,%6,%7},{%8,%9},{%0,%1,%2,%3};"
        : "+f"(d[0]),"+f"(d[1]),"+f"(d[2]),"+f"(d[3])
        : "r"(a[0]),"r"(a[1]),"r"(a[2]),"r"(a[3]),"r"(b0),"r"(b1));
}
// single-MUFU tanh (MUFU.TANH)
__device__ __forceinline__ float mufu_tanh(float x){
    float r;
    asm("tanh.approx.f32 %0,%1;" : "=f"(r) : "f"(x));
    return r;
}
// sigmoid(x) = 0.5*tanh(0.5x) + 0.5   (1 MUFU)
__device__ __forceinline__ float fast_sigmoid(float x){
    return fmaf(0.5f, mufu_tanh(0.5f * x), 0.5f);
}

// ---------------- prep: convert weights to f16 padded layout ----------------
__global__ void prep_kernel(const float* __restrict__ Whh,
                            const float* __restrict__ W1){
    int i = blockIdx.x * blockDim.x + threadIdx.x;
    int stride = gridDim.x * blockDim.x;
    for (int idx = i; idx < WROWS*HH; idx += stride){
        int row = idx >> 7, k = idx & 127;
        float v = (row < 512) ? Whh[row*HH + k] : W1[(row - 512)*HH + k];
        __half hv = __float2half_rn(v);
        g_W16[row*WSTRIDE + k] = *(unsigned short*)&hv;
    }
}

// ---------------- main persistent LSTM kernel ----------------
__global__ __launch_bounds__(NTHR, 1)
void lstm_kernel(const float* __restrict__ x,
                 const float* __restrict__ Wih,
                 const float* __restrict__ bih,
                 const float* __restrict__ bhh,
                 const float* __restrict__ b1,
                 const float* __restrict__ W2,
                 const float* __restrict__ b2,
                 float* __restrict__ out){
    extern __shared__ char sm[];
    const uint32_t smb = smem_u32(sm);
    const int tid  = threadIdx.x;
    const int lane = tid & 31;
    const int w    = tid >> 5;          // warp 0..7, owns units 16w..16w+15
    const int b0   = blockIdx.x * BT;
    float* x_sh = (float*)(sm + OFF_X);

    // ---- stage W (f16, 174080 B) via cp.async; x; zero h buffer 0 ----
    for (int i = tid*16; i < WBYTES; i += NTHR*16)
        cp_async16(sm + OFF_W + i, (const char*)g_W16 + i);
    asm volatile("cp.async.commit_group;" ::: "memory");
    for (int idx = tid; idx < TT*BT; idx += NTHR){
        int t = idx >> 5, b = idx & 31;
        x_sh[t*32 + b] = x[(size_t)(b0 + b)*TT + t];
    }
    for (int i = tid; i < HBYTES/4; i += NTHR)
        ((float*)(sm + OFF_H))[i] = 0.0f;
    asm volatile("cp.async.wait_group 0;" ::: "memory");
    __syncthreads();

    // ---- per-thread constants ----
    const int u0 = 16*w + (lane >> 2);
    const int u1 = u0 + 8;
    float wi[4][2], bs[4][2];
    #pragma unroll
    for (int g = 0; g < 4; g++){
        wi[g][0] = Wih[g*HH + u0];
        wi[g][1] = Wih[g*HH + u1];
        bs[g][0] = bih[g*HH + u0] + bhh[g*HH + u0];
        bs[g][1] = bih[g*HH + u1] + bhh[g*HH + u1];
    }
    float c0[8], c1[8];
    #pragma unroll
    for (int i = 0; i < 8; i++){ c0[i] = 0.0f; c1[i] = 0.0f; }

    // ldmatrix address bases
    uint32_t Abase[4];
    #pragma unroll
    for (int mt = 0; mt < 4; mt++)
        Abase[mt] = smb + OFF_W +
            (uint32_t)(((mt*128 + 16*w + (lane & 15))*WSTRIDE + (lane >> 4)*8) * 2);
    const uint32_t AbaseT = smb + OFF_W +
            (uint32_t)(((512 + 16*w + (lane & 15))*WSTRIDE + (lane >> 4)*8) * 2);
    const uint32_t Brow = (uint32_t)((lane & 7) + ((lane >> 3) & 1)*8);
    const uint32_t Bb0  = smb + OFF_H + Brow*(HSTRIDE*2) + (uint32_t)((lane >> 4)*8)*2;
    const uint32_t Bb1  = Bb0 + 32;     // n0 = 16
    const int bq = 2*(lane & 3);        // batch base within n8 tile

    uint32_t bsel = 0;                  // byte offset of current read h buffer
    for (int t = 0; t < TT; t++){
        // init accumulators with bias + x_t * w_in
        float acc[4][4][4];
        float xv[4][2];
        #pragma unroll
        for (int nt = 0; nt < 4; nt++){
            xv[nt][0] = x_sh[t*32 + 8*nt + bq];
            xv[nt][1] = x_sh[t*32 + 8*nt + bq + 1];
        }
        #pragma unroll
        for (int mt = 0; mt < 4; mt++)
            #pragma unroll
            for (int nt = 0; nt < 4; nt++){
                acc[mt][nt][0] = fmaf(xv[nt][0], wi[mt][0], bs[mt][0]);
                acc[mt][nt][1] = fmaf(xv[nt][1], wi[mt][0], bs[mt][0]);
                acc[mt][nt][2] = fmaf(xv[nt][0], wi[mt][1], bs[mt][1]);
                acc[mt][nt][3] = fmaf(xv[nt][1], wi[mt][1], bs[mt][1]);
            }

        // gates += W @ h   (K = 128, 8 k-chunks)
        const uint32_t Bc0 = Bb0 + bsel, Bc1 = Bb1 + bsel;
        #pragma unroll
        for (int kc = 0; kc < 8; kc++){
            uint32_t bfr0[4], bfr1[4];
            ldsm4t(bfr0, Bc0 + kc*(16*HSTRIDE*2));
            ldsm4t(bfr1, Bc1 + kc*(16*HSTRIDE*2));
            #pragma unroll
            for (int mt = 0; mt < 4; mt++){
                uint32_t a[4];
                ldsm4(a, Abase[mt] + kc*32);
                mma16816(acc[mt][0], a, bfr0[0], bfr0[1]);
                mma16816(acc[mt][1], a, bfr0[2], bfr0[3]);
                mma16816(acc[mt][2], a, bfr1[0], bfr1[1]);
                mma16816(acc[mt][3], a, bfr1[2], bfr1[3]);
            }
        }

        // elementwise LSTM update (all 4 gates thread-local), write h to other buffer
        const uint32_t wsel = bsel ^ HBYTES;
        #pragma unroll
        for (int nt = 0; nt < 4; nt++){
            float hv0[2], hv1[2];
            #pragma unroll
            for (int j = 0; j < 2; j++){
                int ci = nt*2 + j;
                {   // unit u0
                    float iv = fast_sigmoid(acc[0][nt][j]);
                    float fv = fast_sigmoid(acc[1][nt][j]);
                    float gv = mufu_tanh   (acc[2][nt][j]);
                    float ov = fast_sigmoid(acc[3][nt][j]);
                    float cv = fv * c0[ci] + iv * gv;
                    c0[ci] = cv;
                    hv0[j] = ov * mufu_tanh(cv);
                }
                {   // unit u1
                    float iv = fast_sigmoid(acc[0][nt][2+j]);
                    float fv = fast_sigmoid(acc[1][nt][2+j]);
                    float gv = mufu_tanh   (acc[2][nt][2+j]);
                    float ov = fast_sigmoid(acc[3][nt][2+j]);
                    float cv = fv * c1[ci] + iv * gv;
                    c1[ci] = cv;
                    hv1[j] = ov * mufu_tanh(cv);
                }
            }
            int boff = (8*nt + bq)*2;
            *(half2*)(sm + OFF_H + wsel + u0*(HSTRIDE*2) + boff) =
                __floats2half2_rn(hv0[0], hv0[1]);
            *(half2*)(sm + OFF_H + wsel + u1*(HSTRIDE*2) + boff) =
                __floats2half2_rn(hv1[0], hv1[1]);
        }
        __syncthreads();
        bsel = wsel;
    }
    // final h is in buffer with byte-offset bsel (= 0 for TT even)

    // ---- MLP head: r1 = relu(W1 @ h + b1) via the same MMA path ----
    float racc[4][4];
    {
        float bv0 = b1[u0], bv1 = b1[u1];
        #pragma unroll
        for (int nt = 0; nt < 4; nt++){
            racc[nt][0] = bv0; racc[nt][1] = bv0;
            racc[nt][2] = bv1; racc[nt][3] = bv1;
        }
    }
    {
        const uint32_t Bc0 = Bb0 + bsel, Bc1 = Bb1 + bsel;
        #pragma unroll
        for (int kc = 0; kc < 8; kc++){
            uint32_t bfr0[4], bfr1[4];
            ldsm4t(bfr0, Bc0 + kc*(16*HSTRIDE*2));
            ldsm4t(bfr1, Bc1 + kc*(16*HSTRIDE*2));
            uint32_t a[4];
            ldsm4(a, AbaseT + kc*32);
            mma16816(racc[0], a, bfr0[0], bfr0[1]);
            mma16816(racc[1], a, bfr0[2], bfr0[3]);
            mma16816(racc[2], a, bfr1[0], bfr1[1]);
            mma16816(racc[3], a, bfr1[2], bfr1[3]);
        }
    }
    __syncthreads();            // x_sh reads done; reuse as r1_sh
    float* r1_sh = (float*)(sm + OFF_X);   // [b][n] f32
    #pragma unroll
    for (int nt = 0; nt < 4; nt++)
        #pragma unroll
        for (int j = 0; j < 2; j++){
            int b = 8*nt + bq + j;
            r1_sh[b*HH + u0] = fmaxf(racc[nt][j],     0.0f);
            r1_sh[b*HH + u1] = fmaxf(racc[nt][2 + j], 0.0f);
        }
    __syncthreads();
    // stage W2 (5x128 f32) into h region (done with h)
    float* w2sh = (float*)(sm + OFF_H);
    for (int idx = tid; idx < 5*HH; idx += NTHR) w2sh[idx] = W2[idx];
    __syncthreads();

    // ---- r2 = r1 @ W2^T + b2; log_softmax (one thread per batch) ----
    if (tid < BT){
        const int b = tid;
        float r2[5];
        #pragma unroll
        for (int o = 0; o < 5; o++) r2[o] = b2[o];
        for (int kk = 0; kk < HH; kk++){
            int k = (kk + b*4) & (HH - 1);
            float v = r1_sh[b*HH + k];
            #pragma unroll
            for (int o = 0; o < 5; o++) r2[o] = fmaf(v, w2sh[o*HH + k], r2[o]);
        }
        float m = r2[0];
        #pragma unroll
        for (int o = 1; o < 5; o++) m = fmaxf(m, r2[o]);
        float s = 0.0f;
        #pragma unroll
        for (int o = 0; o < 5; o++) s += __expf(r2[o] - m);
        float l = m + __logf(s);
        #pragma unroll
        for (int o = 0; o < 5; o++)
            out[(size_t)(b0 + b)*5 + o] = r2[o] - l;
    }
}

extern "C" void kernel_launch(void* const* d_in, const int* in_sizes, int n_in,
                              void* d_out, int out_size){
    const float* x   = (const float*)d_in[0];
    const float* Wih = (const float*)d_in[1];
    const float* Whh = (const float*)d_in[2];
    const float* bih = (const float*)d_in[3];
    const float* bhh = (const float*)d_in[4];
    const float* W1  = (const float*)d_in[5];
    const float* b1  = (const float*)d_in[6];
    const float* W2  = (const float*)d_in[7];
    const float* b2  = (const float*)d_in[8];
    float* out = (float*)d_out;

    prep_kernel<<<128, 256>>>(Whh, W1);

    cudaFuncSetAttribute(lstm_kernel,
                         cudaFuncAttributeMaxDynamicSharedMemorySize, SMEM_BYTES);
    lstm_kernel<<<NCTA, NTHR, SMEM_BYTES>>>(x, Wih, bih, bhh, b1, W2, b2, out);
}